// round 15
// baseline (speedup 1.0000x reference)
#include <cuda_runtime.h>
#include <cuda_fp16.h>
#include <cstdint>

// Problem constants
#define NN 50000
#define NNPAD 50048              // 391*128; rows NN..NNPAD stay zero (zero-init)
#define DD 256
#define RR 16
#define EE 800000
#define KK (17 * DD)             // 4352 B^T rows: 16 relations + self
#define NBINS (17 * NN)          // 850000 (rel-major pair bins; rel 16 = self)
#define MAXT 6700                // >= ceil(NBINS/128) + 17
#define SCAN_B 1024
#define NBLK_P ((NBINS + SCAN_B - 1) / SCAN_B)   // 831
#define NBLK_D ((NN + SCAN_B - 1) / SCAN_B)      // 49

// Scratch (device globals; zero-initialized at load; allocation-free)
__device__ __half    g_xh[(size_t)NNPAD * DD];     // x fp16 (+zero pad row NN)
__device__ __half    g_bt[(size_t)KK * DD];        // B^T fp16 [j][k]
__device__ __half    g_msgs[(size_t)NBINS * DD];   // <=435MB compact messages
__device__ int       g_pflag[NBINS];               // pair used flags
__device__ int       g_pidx[NBINS];                // scanned -> compact index
__device__ int       g_plist[NBINS];               // compact p -> src
__device__ int       g_hist[NN];                   // dst degree / cursor
__device__ int       g_start[NN];                  // dst start offsets
__device__ int       g_bsumA[1024], g_boffA[1024]; // pair-scan block sums
__device__ int       g_bsumB[64],  g_boffB[64];    // dst-scan block sums
__device__ int       g_tile_rel[MAXT], g_tile_p0[MAXT], g_tile_pend[MAXT];
__device__ int       g_ntiles;
__device__ int       g_seg16;                      // compact base of self segment
__device__ uint32_t  g_edges[EE];                  // dst-sorted msg indices

// ---------------------------------------------------------------------------
__device__ __forceinline__ uint32_t smem_u32(const void* p) {
    uint32_t a;
    asm("{ .reg .u64 t; cvta.to.shared.u64 t, %1; cvt.u32.u64 %0, t; }" : "=r"(a) : "l"(p));
    return a;
}

#define LDSM4(r, addr)                                                        \
    asm volatile("ldmatrix.sync.aligned.m8n8.x4.shared.b16 {%0,%1,%2,%3}, [%4];" \
        : "=r"((r)[0]), "=r"((r)[1]), "=r"((r)[2]), "=r"((r)[3]) : "r"(addr))

#define MMA(d, a, b)                                                          \
    asm volatile("mma.sync.aligned.m16n8k16.row.col.f32.f16.f16.f32 "         \
        "{%0,%1,%2,%3}, {%4,%5,%6,%7}, {%8,%9}, {%0,%1,%2,%3};"               \
        : "+f"((d)[0]), "+f"((d)[1]), "+f"((d)[2]), "+f"((d)[3])              \
        : "r"((a)[0]), "r"((a)[1]), "r"((a)[2]), "r"((a)[3]),                 \
          "r"((b)[0]), "r"((b)[1]))

#define CP16(dst, src) asm volatile("cp.async.cg.shared.global [%0], [%1], 16;" :: "r"(dst), "l"(src))
#define CP_COMMIT()    asm volatile("cp.async.commit_group;" ::: "memory")
#define CP_WAIT(n)     asm volatile("cp.async.wait_group %0;" :: "n"(n) : "memory")

// ---------------------------------------------------------------------------
// Prep A (side stream): x fp32 -> fp16, B^T fp16 build
// ---------------------------------------------------------------------------
__global__ void cvtx_kernel(const float* __restrict__ x) {
    long long i = (long long)blockIdx.x * blockDim.x + threadIdx.x;
    if (i >= (long long)NN * DD) return;
    g_xh[i] = __float2half_rn(x[i]);
}

__global__ void buildbt_kernel(const float* __restrict__ wr, const float* __restrict__ ws) {
    int idx = blockIdx.x * blockDim.x + threadIdx.x;
    if (idx >= KK * DD) return;
    int j = idx >> 8;
    int k = idx & 255;
    float w;
    if (j < RR * DD) {
        int r = j >> 8, h = j & 255;
        w = wr[((size_t)r * DD + k) * DD + h];
    } else {
        w = ws[(size_t)k * DD + (j - RR * DD)];
    }
    g_bt[idx] = __float2half_rn(w);
}

// ---------------------------------------------------------------------------
// Main chain: flag init (self bins pre-flagged) + hist zero
// ---------------------------------------------------------------------------
__global__ void initAB_kernel() {
    int i = blockIdx.x * blockDim.x + threadIdx.x;
    if (i < NBINS) g_pflag[i] = (i >= RR * NN) ? 1 : 0;
    if (i < NN) g_hist[i] = 0;
}

// ---------------------------------------------------------------------------
// Flag used (src,rel) pairs + dst degree histogram
// ---------------------------------------------------------------------------
__global__ void flag_hist_kernel(const int* __restrict__ ei, const int* __restrict__ et) {
    int e = blockIdx.x * blockDim.x + threadIdx.x;
    if (e >= EE) return;
    int src = ei[e], dst = ei[EE + e], rel = et[e];
    if ((unsigned)src >= NN || (unsigned)dst >= NN || (unsigned)rel >= RR) return;
    g_pflag[rel * NN + src] = 1;
    atomicAdd(&g_hist[dst], 1);
}

// ---------------------------------------------------------------------------
// Scans. __device__ symbols dereferenced in device code only (R11 lesson).
//   which=0: pairs  (g_pflag -> g_pidx, sums g_bsumA)
//   which=1: dst    (g_hist  -> g_start, sums g_bsumB)
// ---------------------------------------------------------------------------
__global__ void scan_blocks(int which) {
    const int* in  = which ? g_hist  : g_pflag;
    int*       out = which ? g_start : g_pidx;
    int*      bsum = which ? g_bsumB : g_bsumA;
    const int n    = which ? NN      : NBINS;
    __shared__ int sh_w[32];
    const int tid = threadIdx.x, lane = tid & 31, warp = tid >> 5;
    int i = blockIdx.x * SCAN_B + tid;
    int v = (i < n) ? in[i] : 0;
    int incl = v;
#pragma unroll
    for (int off = 1; off < 32; off <<= 1) {
        int t = __shfl_up_sync(0xFFFFFFFF, incl, off);
        if (lane >= off) incl += t;
    }
    if (lane == 31) sh_w[warp] = incl;
    __syncthreads();
    if (warp == 0) {
        int wv = sh_w[lane];
        int wi = wv;
#pragma unroll
        for (int off = 1; off < 32; off <<= 1) {
            int t = __shfl_up_sync(0xFFFFFFFF, wi, off);
            if (lane >= off) wi += t;
        }
        sh_w[lane] = wi - wv;
    }
    __syncthreads();
    int excl = sh_w[warp] + incl - v;
    if (i < n) out[i] = excl;
    if (tid == SCAN_B - 1) bsum[blockIdx.x] = excl + v;
}

__global__ void scan_tops(int which) {
    const int* bsum = which ? g_bsumB : g_bsumA;
    int*       boff = which ? g_boffB : g_boffA;
    const int  nblk = which ? NBLK_D  : NBLK_P;
    const int lane = threadIdx.x;        // 32 threads
    int carry = 0;
    for (int base = 0; base < nblk; base += 32) {
        int t = base + lane;
        int v = (t < nblk) ? bsum[t] : 0;
        int incl = v;
#pragma unroll
        for (int off = 1; off < 32; off <<= 1) {
            int s = __shfl_up_sync(0xFFFFFFFF, incl, off);
            if (lane >= off) incl += s;
        }
        if (t < nblk) boff[t] = carry + incl - v;
        carry += __shfl_sync(0xFFFFFFFF, incl, 31);
    }
}

// finalize pairs: g_pidx += boffA, and emit plist in the same pass
__global__ void finalizeA_kernel() {
    int i = blockIdx.x * blockDim.x + threadIdx.x;
    if (i >= NBINS) return;
    int p = g_pidx[i] + g_boffA[i >> 10];
    g_pidx[i] = p;
    if (g_pflag[i]) {
        int rel = i / NN;
        g_plist[p] = i - rel * NN;
    }
}

__global__ void scan_addB() {               // dst: finalize g_start, init cursor
    int i = blockIdx.x * blockDim.x + threadIdx.x;
    if (i >= NN) return;
    int s = g_start[i] + g_boffB[i >> 10];
    g_start[i] = s;
    g_hist[i] = s;
}

// ---------------------------------------------------------------------------
// Tile list: segments r=0..16 cut into 128-row tiles. One block.
// ---------------------------------------------------------------------------
__global__ void tiles_kernel() {
    __shared__ int s[17], e[17], nt[17], ts[18];
    const int tid = threadIdx.x;
    if (tid < 17) {
        s[tid] = g_pidx[(size_t)tid * NN];
        e[tid] = (tid == 16) ? (g_pidx[NBINS - 1] + 1) : g_pidx[(size_t)(tid + 1) * NN];
        nt[tid] = (e[tid] - s[tid] + 127) >> 7;
    }
    __syncthreads();
    if (tid == 0) {
        ts[0] = 0;
        for (int r = 0; r < 17; ++r) ts[r + 1] = ts[r] + nt[r];
        g_ntiles = ts[17];
        g_seg16 = s[16];
    }
    __syncthreads();
    for (int r = 0; r < 17; ++r) {
        for (int k = tid; k < nt[r]; k += blockDim.x) {
            int t = ts[r] + k;
            int p0 = s[r] + k * 128;
            g_tile_rel[t] = r;
            g_tile_p0[t] = p0;
            int pe = p0 + 128;
            g_tile_pend[t] = pe < e[r] ? pe : e[r];
        }
    }
}

// ---------------------------------------------------------------------------
// Reorder edges into dst-sorted message-index list
// ---------------------------------------------------------------------------
__global__ void reorder_kernel(const int* __restrict__ ei, const int* __restrict__ et) {
    int e = blockIdx.x * blockDim.x + threadIdx.x;
    if (e >= EE) return;
    int src = ei[e], dst = ei[EE + e], rel = et[e];
    if ((unsigned)src >= NN || (unsigned)dst >= NN || (unsigned)rel >= RR) return;
    int pos = atomicAdd(&g_hist[dst], 1);
    g_edges[pos] = (uint32_t)g_pidx[rel * NN + src];
}

// ---------------------------------------------------------------------------
// Compacted GEMM, tile 128x256: per tile, 128 gathered x-rows @ full W_seg.
// 8 warps at 64x64 warp tiles (2M x 4N). BK=64, 4 chunks, cp.async dbl buf.
// SMEM per buffer: A 128x144B (18432) + B 256x144B (36864) = 55296; x2.
// One CTA/SM (110.6KB smem); ~190 regs/thread.
// ---------------------------------------------------------------------------
#define A_PL 18432
#define B_PL 36864
#define BUF_OFF 55296
#define SMEM_MAIN 110592
#define SMEM_BYTES (SMEM_MAIN + 512)

__global__ void __launch_bounds__(256, 1) mma_gemm_kernel() {
    extern __shared__ char sm[];
    int* sh_src = (int*)(sm + SMEM_MAIN);
    const uint32_t sb = smem_u32(sm);
    const int tid = threadIdx.x, warp = tid >> 5, lane = tid & 31;
    const int wm = warp & 1, wn = warp >> 1;          // 2 x 4 warp grid
    const int ty = blockIdx.x;
    if (ty >= g_ntiles) return;
    const int rel = g_tile_rel[ty];
    const int p0 = g_tile_p0[ty];
    const int pend = g_tile_pend[ty];

    if (tid < 128) {
        int p = p0 + tid;
        sh_src[tid] = (p < pend) ? g_plist[p] : NN;   // NN = zero pad row
    }
    __syncthreads();

    float acc[4][8][4];
#pragma unroll
    for (int a = 0; a < 4; ++a)
#pragma unroll
        for (int b = 0; b < 8; ++b)
#pragma unroll
            for (int c = 0; c < 4; ++c) acc[a][b][c] = 0.f;

    // chunk loader: 3072 x 16B cp.async (A 1024, B 2048) -> 12/thread
    auto load = [&](int c, int b) {
        const int kOff = c * 64;
        const uint32_t dbase = sb + b * BUF_OFF;
#pragma unroll
        for (int i = 0; i < 12; ++i) {
            int idx = tid + i * 256;                 // 0..3071
            if (idx < 1024) {                        // A: 128 rows x 8 vec
                int r = idx >> 3, v = idx & 7;
                CP16(dbase + r * 144 + v * 16,
                     g_xh + (size_t)sh_src[r] * DD + kOff + v * 8);
            } else {                                 // B: 256 rows x 8 vec
                int i2 = idx - 1024;
                int r = i2 >> 3, v = i2 & 7;
                CP16(dbase + A_PL + r * 144 + v * 16,
                     g_bt + (size_t)(rel * DD + r) * DD + kOff + v * 8);
            }
        }
    };

    auto compute = [&](int b) {
        const uint32_t Ab = sb + b * BUF_OFF;
        const uint32_t Bb = Ab + A_PL;
#pragma unroll
        for (int ks = 0; ks < 4; ++ks) {
            uint32_t ah[4][4];
            const int arow = wm * 64 + (lane & 15);
            const uint32_t acol = ((lane >> 4) * 16) + ks * 32;
#pragma unroll
            for (int mt = 0; mt < 4; ++mt) {
                uint32_t ad = Ab + (uint32_t)(arow + mt * 16) * 144 + acol;
                LDSM4(ah[mt], ad);
            }
            uint32_t bh[4][4];
            const int brow = (lane & 7) + ((lane >> 4) << 3);
            const uint32_t bcol = (((lane >> 3) & 1) * 16) + ks * 32;
#pragma unroll
            for (int ng = 0; ng < 4; ++ng) {
                uint32_t bd = Bb + (uint32_t)(wn * 64 + ng * 16 + brow) * 144 + bcol;
                LDSM4(bh[ng], bd);
            }
#pragma unroll
            for (int mt = 0; mt < 4; ++mt)
#pragma unroll
                for (int nt = 0; nt < 8; ++nt) {
                    int ng = nt >> 1, j = nt & 1;
                    MMA(acc[mt][nt], ah[mt], (&bh[ng][j * 2]));
                }
        }
    };

    load(0, 0);
    CP_COMMIT();
    load(1, 1);
    CP_COMMIT();
#pragma unroll 1
    for (int c = 0; c < 4; ++c) {
        if (c < 3) { CP_WAIT(1); } else { CP_WAIT(0); }
        __syncthreads();
        compute(c & 1);
        __syncthreads();
        if (c + 2 < 4) {
            load(c + 2, c & 1);
            CP_COMMIT();
        }
    }

    // epilogue: fp16 message rows (full 256 cols per tile)
#pragma unroll
    for (int mt = 0; mt < 4; ++mt) {
        int rr = wm * 64 + mt * 16 + (lane >> 2);
#pragma unroll
        for (int nt = 0; nt < 8; ++nt) {
            int col = wn * 64 + nt * 8 + 2 * (lane & 3);
            __half2 v01 = __floats2half2_rn(acc[mt][nt][0], acc[mt][nt][1]);
            __half2 v23 = __floats2half2_rn(acc[mt][nt][2], acc[mt][nt][3]);
            if (p0 + rr < pend)
                *(__half2*)(g_msgs + (size_t)(p0 + rr) * DD + col) = v01;
            if (p0 + rr + 8 < pend)
                *(__half2*)(g_msgs + (size_t)(p0 + rr + 8) * DD + col) = v23;
        }
    }
}

// ---------------------------------------------------------------------------
// Gather-reduce + fused epilogue: warp per dst; self row = msgs[seg16 + n].
// Unroll-4 for MLP on the random 512B message stream.
// ---------------------------------------------------------------------------
__device__ __forceinline__ void acc_msg(float* acc, const uint4& m) {
    float2 f0 = __half22float2(*(__half2*)&m.x);
    float2 f1 = __half22float2(*(__half2*)&m.y);
    float2 f2 = __half22float2(*(__half2*)&m.z);
    float2 f3 = __half22float2(*(__half2*)&m.w);
    acc[0] += f0.x; acc[1] += f0.y; acc[2] += f1.x; acc[3] += f1.y;
    acc[4] += f2.x; acc[5] += f2.y; acc[6] += f3.x; acc[7] += f3.y;
}

__global__ void __launch_bounds__(256) gather_kernel(const float* __restrict__ bias,
                                                     float* __restrict__ out) {
    int n = blockIdx.x * 8 + (threadIdx.x >> 5);
    if (n >= NN) return;
    const int lane = threadIdx.x & 31;

    float acc[8];
#pragma unroll
    for (int j = 0; j < 8; ++j) acc[j] = 0.f;

    const int beg = g_start[n];
    const int end = g_hist[n];

    int i = beg;
    for (; i + 4 <= end; i += 4) {
        uint32_t u0 = g_edges[i], u1 = g_edges[i + 1];
        uint32_t u2 = g_edges[i + 2], u3 = g_edges[i + 3];
        uint4 m0 = *(const uint4*)(g_msgs + (size_t)u0 * DD + lane * 8);
        uint4 m1 = *(const uint4*)(g_msgs + (size_t)u1 * DD + lane * 8);
        uint4 m2 = *(const uint4*)(g_msgs + (size_t)u2 * DD + lane * 8);
        uint4 m3 = *(const uint4*)(g_msgs + (size_t)u3 * DD + lane * 8);
        acc_msg(acc, m0);
        acc_msg(acc, m1);
        acc_msg(acc, m2);
        acc_msg(acc, m3);
    }
    for (; i < end; ++i) {
        uint32_t u = g_edges[i];
        uint4 m = *(const uint4*)(g_msgs + (size_t)u * DD + lane * 8);
        acc_msg(acc, m);
    }

    // self term
    {
        uint4 m = *(const uint4*)(g_msgs + (size_t)(g_seg16 + n) * DD + lane * 8);
        acc_msg(acc, m);
    }

    const float* bp = bias + lane * 8;
    float* op = out + (size_t)n * DD + lane * 8;
    float4 b0 = *(const float4*)bp, b1 = *(const float4*)(bp + 4);
    float4 o0, o1;
    o0.x = fmaxf(acc[0] + b0.x, 0.f);
    o0.y = fmaxf(acc[1] + b0.y, 0.f);
    o0.z = fmaxf(acc[2] + b0.z, 0.f);
    o0.w = fmaxf(acc[3] + b0.w, 0.f);
    o1.x = fmaxf(acc[4] + b1.x, 0.f);
    o1.y = fmaxf(acc[5] + b1.y, 0.f);
    o1.z = fmaxf(acc[6] + b1.z, 0.f);
    o1.w = fmaxf(acc[7] + b1.w, 0.f);
    *(float4*)op = o0;
    *(float4*)(op + 4) = o1;
}

// ---------------------------------------------------------------------------
extern "C" void kernel_launch(void* const* d_in, const int* in_sizes, int n_in,
                              void* d_out, int out_size) {
    const float* x    = (const float*)d_in[0];
    const int*   ei   = (const int*)d_in[1];     // (2, E) int32
    const int*   et   = (const int*)d_in[2];     // (E,)  int32
    const float* wr   = (const float*)d_in[3];   // (16,256,256)
    const float* ws   = (const float*)d_in[4];   // (256,256)
    const float* bias = (const float*)d_in[5];   // (256,)
    float*       out  = (float*)d_out;           // (50000,256)
    (void)in_sizes; (void)n_in; (void)out_size;

    // Streams/events created once on the uncaptured correctness call (host
    // objects only; no device memory). R14 established this pattern works
    // under the harness's graph capture.
    static cudaStream_t sA = nullptr, sB = nullptr;
    static cudaEvent_t evStart = nullptr, evPrep = nullptr, evFH = nullptr,
                       evFA = nullptr, evJoin = nullptr;
    if (sA == nullptr) {
        cudaStreamCreateWithFlags(&sA, cudaStreamNonBlocking);
        cudaStreamCreateWithFlags(&sB, cudaStreamNonBlocking);
        cudaEventCreateWithFlags(&evStart, cudaEventDisableTiming);
        cudaEventCreateWithFlags(&evPrep, cudaEventDisableTiming);
        cudaEventCreateWithFlags(&evFH, cudaEventDisableTiming);
        cudaEventCreateWithFlags(&evFA, cudaEventDisableTiming);
        cudaEventCreateWithFlags(&evJoin, cudaEventDisableTiming);
    }

    cudaFuncSetAttribute(mma_gemm_kernel, cudaFuncAttributeMaxDynamicSharedMemorySize, SMEM_BYTES);

    // ---- fork side stream A: x/W conversion, hidden under the index chain ----
    cudaEventRecord(evStart, 0);
    cudaStreamWaitEvent(sA, evStart, 0);
    cvtx_kernel<<<(NN * DD + 255) / 256, 256, 0, sA>>>(x);
    buildbt_kernel<<<(KK * DD + 255) / 256, 256, 0, sA>>>(wr, ws);
    cudaEventRecord(evPrep, sA);

    // ---- main: pair/dst index chain ----
    initAB_kernel<<<(NBINS + 255) / 256, 256>>>();
    flag_hist_kernel<<<(EE + 255) / 256, 256>>>(ei, et);
    cudaEventRecord(evFH, 0);

    // side stream B: dst scan (needs hist), hidden under pair chain + GEMM
    cudaStreamWaitEvent(sB, evFH, 0);
    scan_blocks<<<NBLK_D, SCAN_B, 0, sB>>>(1);
    scan_tops<<<1, 32, 0, sB>>>(1);
    scan_addB<<<(NN + 255) / 256, 256, 0, sB>>>();

    // main: pair compaction
    scan_blocks<<<NBLK_P, SCAN_B>>>(0);
    scan_tops<<<1, 32>>>(0);
    finalizeA_kernel<<<(NBINS + 255) / 256, 256>>>();
    cudaEventRecord(evFA, 0);

    // side stream B: reorder needs finalizeA's pidx
    cudaStreamWaitEvent(sB, evFA, 0);
    reorder_kernel<<<(EE + 255) / 256, 256, 0, sB>>>(ei, et);
    cudaEventRecord(evJoin, sB);

    // main: tiles + GEMM (needs prep A)
    tiles_kernel<<<1, 256>>>();
    cudaStreamWaitEvent(0, evPrep, 0);
    mma_gemm_kernel<<<MAXT, 256, SMEM_BYTES>>>();

    // join dst chain, then gather + self + bias + relu
    cudaStreamWaitEvent(0, evJoin, 0);
    gather_kernel<<<(NN + 7) / 8, 256>>>(bias, out);
}